// round 3
// baseline (speedup 1.0000x reference)
#include <cuda_runtime.h>
#include <math.h>

#define NN 50000
#define EE 800000
#define MM (EE + NN)
#define HH 8
#define FF 128

// ---------------- scratch (static __device__, no allocation) ----------------
__device__ __align__(16) float g_ha[NN * FF];   // post-GEMM h (per layer)
__device__ __align__(16) float g_hb[NN * FF];   // post-aggregation h (layer output)
__device__ __align__(16) float g_es[NN * HH];
__device__ __align__(16) float g_ed[NN * HH];
__device__ __align__(16) float g_w[MM * HH];    // per-edge per-head exp weights
__device__ __align__(16) float g_dnm[NN * HH];  // softmax denominators
__device__ int   g_src[MM];                     // src ids sorted by dst (CSR)
__device__ int   g_rowptr[NN + 1];
__device__ int   g_cnt[NN];
__device__ int   g_cur[NN];
__device__ int   g_is64;                        // edge_index dtype flag

// ---------------- dtype detection ----------------
// jnp.int64 silently downcasts to int32 when x64 is disabled. Detect on device:
// interpret first 64 entries as int64; if all in [0, NN) it's genuinely int64
// (an int32 buffer read this way yields lo + hi<<32 with hi~U[0,50000), so the
// false-accept probability is (1/50000)^64 ~ 0).
__global__ void detect_kernel(const void* __restrict__ ei) {
    const long long* p64 = (const long long*)ei;
    int is64 = 1;
    for (int i = 0; i < 64; i++) {
        long long v = p64[i];  // 512B read, within buffer for either dtype
        if (v < 0 || v >= NN) { is64 = 0; break; }
    }
    g_is64 = is64;
}

__device__ __forceinline__ int load_idx(const void* __restrict__ ei, int pos) {
    if (g_is64) return (int)((const long long*)ei)[pos];
    return ((const int*)ei)[pos];
}

// ---------------- CSR build ----------------
__global__ void zero_cnt_kernel() {
    int i = blockIdx.x * blockDim.x + threadIdx.x;
    if (i < NN) g_cnt[i] = 0;
}

__global__ void count_kernel(const void* __restrict__ ei) {
    int i = blockIdx.x * blockDim.x + threadIdx.x;
    if (i >= MM) return;
    int dst = (i < EE) ? load_idx(ei, EE + i) : (i - EE);
    atomicAdd(&g_cnt[dst], 1);
}

__global__ void scan_kernel() {
    __shared__ int sums[1024];
    int tid = threadIdx.x;
    const int chunk = (NN + 1023) / 1024;
    int b = tid * chunk;
    int e = b + chunk; if (e > NN) e = NN;
    if (b > NN) b = NN;
    int s = 0;
    for (int i = b; i < e; i++) s += g_cnt[i];
    sums[tid] = s;
    __syncthreads();
    // Hillis-Steele inclusive scan
    for (int off = 1; off < 1024; off <<= 1) {
        int v = (tid >= off) ? sums[tid - off] : 0;
        __syncthreads();
        sums[tid] += v;
        __syncthreads();
    }
    int offset = (tid == 0) ? 0 : sums[tid - 1];
    for (int i = b; i < e; i++) {
        g_rowptr[i] = offset;
        g_cur[i] = offset;
        offset += g_cnt[i];
    }
    if (tid == 1023) g_rowptr[NN] = sums[1023];
}

__global__ void fill_kernel(const void* __restrict__ ei) {
    int i = blockIdx.x * blockDim.x + threadIdx.x;
    if (i >= MM) return;
    int src, dst;
    if (i < EE) { src = load_idx(ei, i); dst = load_idx(ei, EE + i); }
    else        { src = dst = i - EE; }
    int pos = atomicAdd(&g_cur[dst], 1);
    g_src[pos] = src;
}

// ---------------- fused SGEMM + attention projections ----------------
// h = X @ W  [N,128]; e_src[n,h] = <h[n,h,:], a_src[h,:]>; same for e_dst.
#define BM 64
#define BK 32

__global__ __launch_bounds__(256)
void gemm_attn_kernel(const float* __restrict__ Xext, int useExt,
                      const float* __restrict__ W,
                      const float* __restrict__ asrc,
                      const float* __restrict__ adst) {
    __shared__ float Xs[BK][BM + 1];        // transposed x tile
    __shared__ float Ws_s[BK][128];
    __shared__ float es_sh[BM][HH];
    __shared__ float ed_sh[BM][HH];

    const float* X = useExt ? Xext : g_hb;
    int tid = threadIdx.x;
    int block_m = blockIdx.x * BM;

    for (int i = tid; i < BM * HH; i += 256) {
        (&es_sh[0][0])[i] = 0.0f;
        (&ed_sh[0][0])[i] = 0.0f;
    }

    int tm = tid >> 4;   // 0..15 -> rows tm*4..+3
    int tn = tid & 15;   // cols tn*8..+7

    float acc[4][8];
#pragma unroll
    for (int i = 0; i < 4; i++)
#pragma unroll
        for (int j = 0; j < 8; j++) acc[i][j] = 0.0f;

    for (int k0 = 0; k0 < FF; k0 += BK) {
        // load W tile 32x128
#pragma unroll
        for (int i = 0; i < 4; i++) {
            int idx = (tid + i * 256) * 4;       // 0..4092
            int kk = idx >> 7, cc = idx & 127;
            float4 v = *(const float4*)&W[(k0 + kk) * 128 + cc];
            *(float4*)&Ws_s[kk][cc] = v;
        }
        // load X tile 64x32 (transposed store)
#pragma unroll
        for (int i = 0; i < 2; i++) {
            int idx = (tid + i * 256) * 4;       // 0..2044
            int m = idx >> 5, kk = idx & 31;
            int node = block_m + m;
            float4 v = make_float4(0.f, 0.f, 0.f, 0.f);
            if (node < NN) v = *(const float4*)&X[node * FF + k0 + kk];
            Xs[kk + 0][m] = v.x; Xs[kk + 1][m] = v.y;
            Xs[kk + 2][m] = v.z; Xs[kk + 3][m] = v.w;
        }
        __syncthreads();
#pragma unroll
        for (int k = 0; k < BK; k++) {
            float4 b0 = *(const float4*)&Ws_s[k][tn * 8];
            float4 b1 = *(const float4*)&Ws_s[k][tn * 8 + 4];
            float bv[8] = {b0.x, b0.y, b0.z, b0.w, b1.x, b1.y, b1.z, b1.w};
            float av[4];
#pragma unroll
            for (int i = 0; i < 4; i++) av[i] = Xs[k][tm * 4 + i];
#pragma unroll
            for (int i = 0; i < 4; i++)
#pragma unroll
                for (int j = 0; j < 8; j++) acc[i][j] += av[i] * bv[j];
        }
        __syncthreads();
    }

    // epilogue: store h, accumulate attention projections
    int h = tn >> 1;             // head for this thread's 8 cols
    float as_[8], ad_[8];
#pragma unroll
    for (int j = 0; j < 8; j++) {
        int c = (tn * 8 + j) & 15;
        as_[j] = asrc[h * 16 + c];
        ad_[j] = adst[h * 16 + c];
    }
#pragma unroll
    for (int i = 0; i < 4; i++) {
        int m = tm * 4 + i;
        int node = block_m + m;
        if (node < NN) {
            float4 o0 = make_float4(acc[i][0], acc[i][1], acc[i][2], acc[i][3]);
            float4 o1 = make_float4(acc[i][4], acc[i][5], acc[i][6], acc[i][7]);
            *(float4*)&g_ha[node * FF + tn * 8] = o0;
            *(float4*)&g_ha[node * FF + tn * 8 + 4] = o1;
            float ps = 0.f, pd = 0.f;
#pragma unroll
            for (int j = 0; j < 8; j++) { ps += acc[i][j] * as_[j]; pd += acc[i][j] * ad_[j]; }
            atomicAdd(&es_sh[m][h], ps);
            atomicAdd(&ed_sh[m][h], pd);
        }
    }
    __syncthreads();
    for (int i = tid; i < BM * HH; i += 256) {
        int node = block_m + (i >> 3);
        if (node < NN) {
            g_es[node * HH + (i & 7)] = (&es_sh[0][0])[i];
            g_ed[node * HH + (i & 7)] = (&ed_sh[0][0])[i];
        }
    }
}

// ---------------- per-dst softmax scores (warp per node, no atomics) ----------------
__global__ __launch_bounds__(256)
void attn_scores_kernel() {
    int warp = blockIdx.x * (blockDim.x >> 5) + (threadIdx.x >> 5);
    if (warp >= NN) return;
    int lane = threadIdx.x & 31;
    int head = lane & 7, slot = lane >> 3;
    int r0 = g_rowptr[warp], r1 = g_rowptr[warp + 1];
    float edv = g_ed[warp * HH + head];

    float m = -1e30f;
    for (int e = r0 + slot; e < r1; e += 4) {
        int s = g_src[e];
        float v = g_es[s * HH + head] + edv;
        v = v > 0.f ? v : 0.2f * v;
        m = fmaxf(m, v);
    }
    m = fmaxf(m, __shfl_xor_sync(0xffffffffu, m, 8));
    m = fmaxf(m, __shfl_xor_sync(0xffffffffu, m, 16));

    float d = 0.f;
    for (int e = r0 + slot; e < r1; e += 4) {
        int s = g_src[e];
        float v = g_es[s * HH + head] + edv;
        v = v > 0.f ? v : 0.2f * v;
        float w = __expf(v - m);
        d += w;
        g_w[e * HH + head] = w;
    }
    d += __shfl_xor_sync(0xffffffffu, d, 8);
    d += __shfl_xor_sync(0xffffffffu, d, 16);
    if (lane < 8) g_dnm[warp * HH + lane] = d;
}

// ---------------- weighted gather-aggregate + bias + ELU (warp per node) ----------------
__global__ __launch_bounds__(256)
void aggregate_kernel(const float* __restrict__ bias) {
    int warp = blockIdx.x * (blockDim.x >> 5) + (threadIdx.x >> 5);
    if (warp >= NN) return;
    int lane = threadIdx.x & 31;
    int head = lane >> 2;                  // 4 lanes per head, lane owns channels 4*lane..+3
    int r0 = g_rowptr[warp], r1 = g_rowptr[warp + 1];
    float inv = 1.0f / (g_dnm[warp * HH + head] + 1e-16f);

    float4 acc = make_float4(0.f, 0.f, 0.f, 0.f);
    for (int e = r0; e < r1; e++) {
        int s = g_src[e];
        float w = g_w[e * HH + head];
        float4 hv = *(const float4*)&g_ha[s * FF + lane * 4];
        acc.x += w * hv.x; acc.y += w * hv.y;
        acc.z += w * hv.z; acc.w += w * hv.w;
    }
    float4 b = *(const float4*)&bias[lane * 4];
    float4 o;
    o.x = acc.x * inv + b.x;
    o.y = acc.y * inv + b.y;
    o.z = acc.z * inv + b.z;
    o.w = acc.w * inv + b.w;
    o.x = o.x > 0.f ? o.x : expm1f(o.x);
    o.y = o.y > 0.f ? o.y : expm1f(o.y);
    o.z = o.z > 0.f ? o.z : expm1f(o.z);
    o.w = o.w > 0.f ? o.w : expm1f(o.w);
    *(float4*)&g_hb[warp * FF + lane * 4] = o;
}

// ---------------- final FC: out = h @ fc_w + fc_b  [N,16] ----------------
__global__ __launch_bounds__(256)
void final_fc_kernel(const float* __restrict__ fcw,
                     const float* __restrict__ fcb,
                     float* __restrict__ out) {
    int tid = blockIdx.x * blockDim.x + threadIdx.x;
    int node = tid >> 4;
    int c = tid & 15;
    if (node >= NN) return;
    const float* hr = g_hb + node * FF;
    float acc = fcb[c];
#pragma unroll 8
    for (int k = 0; k < FF; k++) acc += hr[k] * fcw[k * 16 + c];
    out[node * 16 + c] = acc;
}

// ---------------- launch ----------------
extern "C" void kernel_launch(void* const* d_in, const int* in_sizes, int n_in,
                              void* d_out, int out_size) {
    const float* x    = (const float*)d_in[0];
    const float* Ws   = (const float*)d_in[1];   // [3,128,128]
    const float* asrc = (const float*)d_in[2];   // [3,8,16]
    const float* adst = (const float*)d_in[3];
    const float* bias = (const float*)d_in[4];   // [3,128]
    const float* fcw  = (const float*)d_in[5];   // [128,16]
    const float* fcb  = (const float*)d_in[6];   // [16]
    const void*  ei   = (const void*)d_in[7];    // [2,E] int64 OR int32 (detected on device)
    float* out = (float*)d_out;

    // CSR build (once per launch, captured in graph)
    detect_kernel<<<1, 1>>>(ei);
    zero_cnt_kernel<<<(NN + 255) / 256, 256>>>();
    count_kernel<<<(MM + 255) / 256, 256>>>(ei);
    scan_kernel<<<1, 1024>>>();
    fill_kernel<<<(MM + 255) / 256, 256>>>(ei);

    int gemm_blocks = (NN + BM - 1) / BM;
    int warp_blocks = (NN + 7) / 8;

    for (int l = 0; l < 3; l++) {
        gemm_attn_kernel<<<gemm_blocks, 256>>>(x, l == 0 ? 1 : 0,
                                               Ws + l * 128 * 128,
                                               asrc + l * 128,
                                               adst + l * 128);
        attn_scores_kernel<<<warp_blocks, 256>>>();
        aggregate_kernel<<<warp_blocks, 256>>>(bias + l * 128);
    }

    final_fc_kernel<<<(NN * 16 + 255) / 256, 256>>>(fcw, fcb, out);
}

// round 4
// speedup vs baseline: 1.0035x; 1.0035x over previous
#include <cuda_runtime.h>
#include <math.h>

#define NN 50000
#define EE 800000
#define MM (EE + NN)
#define HH 8
#define FF 128

// ---------------- scratch (static __device__, no allocation) ----------------
__device__ __align__(16) float g_ha[NN * FF];   // post-GEMM h (per layer)
__device__ __align__(16) float g_hb[NN * FF];   // post-aggregation h (layer output)
__device__ __align__(16) float g_es[NN * HH];
__device__ __align__(16) float g_ed[NN * HH];
__device__ __align__(16) float g_w[MM * HH];    // per-edge per-head exp weights
__device__ __align__(16) float g_dnm[NN * HH];  // softmax denominators
__device__ int   g_src[MM];                     // src ids sorted by dst (CSR)
__device__ int   g_rowptr[NN + 1];
__device__ int   g_cnt[NN];
__device__ int   g_cur[NN];
__device__ int   g_is64;                        // edge_index dtype flag

// ---------------- dtype detection ----------------
// jnp.int64 silently downcasts to int32 when x64 is disabled. Detect on device:
// interpret first 64 entries as int64; if all in [0, NN) it's genuinely int64
// (an int32 buffer read this way yields lo + hi<<32 with hi~U[0,50000), so the
// false-accept probability is (1/50000)^64 ~ 0).
__global__ void detect_kernel(const void* __restrict__ ei) {
    const long long* p64 = (const long long*)ei;
    int is64 = 1;
    for (int i = 0; i < 64; i++) {
        long long v = p64[i];  // 512B read, within buffer for either dtype
        if (v < 0 || v >= NN) { is64 = 0; break; }
    }
    g_is64 = is64;
}

__device__ __forceinline__ int load_idx(const void* __restrict__ ei, int pos) {
    if (g_is64) return (int)((const long long*)ei)[pos];
    return ((const int*)ei)[pos];
}

// ---------------- CSR build ----------------
__global__ void zero_cnt_kernel() {
    int i = blockIdx.x * blockDim.x + threadIdx.x;
    if (i < NN) g_cnt[i] = 0;
}

__global__ void count_kernel(const void* __restrict__ ei) {
    int i = blockIdx.x * blockDim.x + threadIdx.x;
    if (i >= MM) return;
    int dst = (i < EE) ? load_idx(ei, EE + i) : (i - EE);
    atomicAdd(&g_cnt[dst], 1);
}

__global__ void scan_kernel() {
    __shared__ int sums[1024];
    int tid = threadIdx.x;
    const int chunk = (NN + 1023) / 1024;
    int b = tid * chunk;
    int e = b + chunk; if (e > NN) e = NN;
    if (b > NN) b = NN;
    int s = 0;
    for (int i = b; i < e; i++) s += g_cnt[i];
    sums[tid] = s;
    __syncthreads();
    // Hillis-Steele inclusive scan
    for (int off = 1; off < 1024; off <<= 1) {
        int v = (tid >= off) ? sums[tid - off] : 0;
        __syncthreads();
        sums[tid] += v;
        __syncthreads();
    }
    int offset = (tid == 0) ? 0 : sums[tid - 1];
    for (int i = b; i < e; i++) {
        g_rowptr[i] = offset;
        g_cur[i] = offset;
        offset += g_cnt[i];
    }
    if (tid == 1023) g_rowptr[NN] = sums[1023];
}

__global__ void fill_kernel(const void* __restrict__ ei) {
    int i = blockIdx.x * blockDim.x + threadIdx.x;
    if (i >= MM) return;
    int src, dst;
    if (i < EE) { src = load_idx(ei, i); dst = load_idx(ei, EE + i); }
    else        { src = dst = i - EE; }
    int pos = atomicAdd(&g_cur[dst], 1);
    g_src[pos] = src;
}

// ---------------- fused SGEMM + attention projections ----------------
// h = X @ W  [N,128]; e_src[n,h] = <h[n,h,:], a_src[h,:]>; same for e_dst.
#define BM 64
#define BK 32

__global__ __launch_bounds__(256)
void gemm_attn_kernel(const float* __restrict__ Xext, int useExt,
                      const float* __restrict__ W,
                      const float* __restrict__ asrc,
                      const float* __restrict__ adst) {
    __shared__ float Xs[BK][BM + 1];        // transposed x tile
    __shared__ float Ws_s[BK][128];
    __shared__ float es_sh[BM][HH];
    __shared__ float ed_sh[BM][HH];

    const float* X = useExt ? Xext : g_hb;
    int tid = threadIdx.x;
    int block_m = blockIdx.x * BM;

    for (int i = tid; i < BM * HH; i += 256) {
        (&es_sh[0][0])[i] = 0.0f;
        (&ed_sh[0][0])[i] = 0.0f;
    }

    int tm = tid >> 4;   // 0..15 -> rows tm*4..+3
    int tn = tid & 15;   // cols tn*8..+7

    float acc[4][8];
#pragma unroll
    for (int i = 0; i < 4; i++)
#pragma unroll
        for (int j = 0; j < 8; j++) acc[i][j] = 0.0f;

    for (int k0 = 0; k0 < FF; k0 += BK) {
        // load W tile 32x128
#pragma unroll
        for (int i = 0; i < 4; i++) {
            int idx = (tid + i * 256) * 4;       // 0..4092
            int kk = idx >> 7, cc = idx & 127;
            float4 v = *(const float4*)&W[(k0 + kk) * 128 + cc];
            *(float4*)&Ws_s[kk][cc] = v;
        }
        // load X tile 64x32 (transposed store)
#pragma unroll
        for (int i = 0; i < 2; i++) {
            int idx = (tid + i * 256) * 4;       // 0..2044
            int m = idx >> 5, kk = idx & 31;
            int node = block_m + m;
            float4 v = make_float4(0.f, 0.f, 0.f, 0.f);
            if (node < NN) v = *(const float4*)&X[node * FF + k0 + kk];
            Xs[kk + 0][m] = v.x; Xs[kk + 1][m] = v.y;
            Xs[kk + 2][m] = v.z; Xs[kk + 3][m] = v.w;
        }
        __syncthreads();
#pragma unroll
        for (int k = 0; k < BK; k++) {
            float4 b0 = *(const float4*)&Ws_s[k][tn * 8];
            float4 b1 = *(const float4*)&Ws_s[k][tn * 8 + 4];
            float bv[8] = {b0.x, b0.y, b0.z, b0.w, b1.x, b1.y, b1.z, b1.w};
            float av[4];
#pragma unroll
            for (int i = 0; i < 4; i++) av[i] = Xs[k][tm * 4 + i];
#pragma unroll
            for (int i = 0; i < 4; i++)
#pragma unroll
                for (int j = 0; j < 8; j++) acc[i][j] += av[i] * bv[j];
        }
        __syncthreads();
    }

    // epilogue: store h, accumulate attention projections
    int h = tn >> 1;             // head for this thread's 8 cols
    float as_[8], ad_[8];
#pragma unroll
    for (int j = 0; j < 8; j++) {
        int c = (tn * 8 + j) & 15;
        as_[j] = asrc[h * 16 + c];
        ad_[j] = adst[h * 16 + c];
    }
#pragma unroll
    for (int i = 0; i < 4; i++) {
        int m = tm * 4 + i;
        int node = block_m + m;
        if (node < NN) {
            float4 o0 = make_float4(acc[i][0], acc[i][1], acc[i][2], acc[i][3]);
            float4 o1 = make_float4(acc[i][4], acc[i][5], acc[i][6], acc[i][7]);
            *(float4*)&g_ha[node * FF + tn * 8] = o0;
            *(float4*)&g_ha[node * FF + tn * 8 + 4] = o1;
            float ps = 0.f, pd = 0.f;
#pragma unroll
            for (int j = 0; j < 8; j++) { ps += acc[i][j] * as_[j]; pd += acc[i][j] * ad_[j]; }
            atomicAdd(&es_sh[m][h], ps);
            atomicAdd(&ed_sh[m][h], pd);
        }
    }
    __syncthreads();
    for (int i = tid; i < BM * HH; i += 256) {
        int node = block_m + (i >> 3);
        if (node < NN) {
            g_es[node * HH + (i & 7)] = (&es_sh[0][0])[i];
            g_ed[node * HH + (i & 7)] = (&ed_sh[0][0])[i];
        }
    }
}

// ---------------- per-dst softmax scores (warp per node, no atomics) ----------------
__global__ __launch_bounds__(256)
void attn_scores_kernel() {
    int warp = blockIdx.x * (blockDim.x >> 5) + (threadIdx.x >> 5);
    if (warp >= NN) return;
    int lane = threadIdx.x & 31;
    int head = lane & 7, slot = lane >> 3;
    int r0 = g_rowptr[warp], r1 = g_rowptr[warp + 1];
    float edv = g_ed[warp * HH + head];

    float m = -1e30f;
    for (int e = r0 + slot; e < r1; e += 4) {
        int s = g_src[e];
        float v = g_es[s * HH + head] + edv;
        v = v > 0.f ? v : 0.2f * v;
        m = fmaxf(m, v);
    }
    m = fmaxf(m, __shfl_xor_sync(0xffffffffu, m, 8));
    m = fmaxf(m, __shfl_xor_sync(0xffffffffu, m, 16));

    float d = 0.f;
    for (int e = r0 + slot; e < r1; e += 4) {
        int s = g_src[e];
        float v = g_es[s * HH + head] + edv;
        v = v > 0.f ? v : 0.2f * v;
        float w = __expf(v - m);
        d += w;
        g_w[e * HH + head] = w;
    }
    d += __shfl_xor_sync(0xffffffffu, d, 8);
    d += __shfl_xor_sync(0xffffffffu, d, 16);
    if (lane < 8) g_dnm[warp * HH + lane] = d;
}

// ---------------- weighted gather-aggregate + bias + ELU (warp per node) ----------------
__global__ __launch_bounds__(256)
void aggregate_kernel(const float* __restrict__ bias) {
    int warp = blockIdx.x * (blockDim.x >> 5) + (threadIdx.x >> 5);
    if (warp >= NN) return;
    int lane = threadIdx.x & 31;
    int head = lane >> 2;                  // 4 lanes per head, lane owns channels 4*lane..+3
    int r0 = g_rowptr[warp], r1 = g_rowptr[warp + 1];
    float inv = 1.0f / (g_dnm[warp * HH + head] + 1e-16f);

    float4 acc = make_float4(0.f, 0.f, 0.f, 0.f);
    for (int e = r0; e < r1; e++) {
        int s = g_src[e];
        float w = g_w[e * HH + head];
        float4 hv = *(const float4*)&g_ha[s * FF + lane * 4];
        acc.x += w * hv.x; acc.y += w * hv.y;
        acc.z += w * hv.z; acc.w += w * hv.w;
    }
    float4 b = *(const float4*)&bias[lane * 4];
    float4 o;
    o.x = acc.x * inv + b.x;
    o.y = acc.y * inv + b.y;
    o.z = acc.z * inv + b.z;
    o.w = acc.w * inv + b.w;
    o.x = o.x > 0.f ? o.x : expm1f(o.x);
    o.y = o.y > 0.f ? o.y : expm1f(o.y);
    o.z = o.z > 0.f ? o.z : expm1f(o.z);
    o.w = o.w > 0.f ? o.w : expm1f(o.w);
    *(float4*)&g_hb[warp * FF + lane * 4] = o;
}

// ---------------- final FC: out = h @ fc_w + fc_b  [N,16] ----------------
__global__ __launch_bounds__(256)
void final_fc_kernel(const float* __restrict__ fcw,
                     const float* __restrict__ fcb,
                     float* __restrict__ out) {
    int tid = blockIdx.x * blockDim.x + threadIdx.x;
    int node = tid >> 4;
    int c = tid & 15;
    if (node >= NN) return;
    const float* hr = g_hb + node * FF;
    float acc = fcb[c];
#pragma unroll 8
    for (int k = 0; k < FF; k++) acc += hr[k] * fcw[k * 16 + c];
    out[node * 16 + c] = acc;
}

// ---------------- launch ----------------
extern "C" void kernel_launch(void* const* d_in, const int* in_sizes, int n_in,
                              void* d_out, int out_size) {
    const float* x    = (const float*)d_in[0];
    const float* Ws   = (const float*)d_in[1];   // [3,128,128]
    const float* asrc = (const float*)d_in[2];   // [3,8,16]
    const float* adst = (const float*)d_in[3];
    const float* bias = (const float*)d_in[4];   // [3,128]
    const float* fcw  = (const float*)d_in[5];   // [128,16]
    const float* fcb  = (const float*)d_in[6];   // [16]
    const void*  ei   = (const void*)d_in[7];    // [2,E] int64 OR int32 (detected on device)
    float* out = (float*)d_out;

    // CSR build (once per launch, captured in graph)
    detect_kernel<<<1, 1>>>(ei);
    zero_cnt_kernel<<<(NN + 255) / 256, 256>>>();
    count_kernel<<<(MM + 255) / 256, 256>>>(ei);
    scan_kernel<<<1, 1024>>>();
    fill_kernel<<<(MM + 255) / 256, 256>>>(ei);

    int gemm_blocks = (NN + BM - 1) / BM;
    int warp_blocks = (NN + 7) / 8;

    for (int l = 0; l < 3; l++) {
        gemm_attn_kernel<<<gemm_blocks, 256>>>(x, l == 0 ? 1 : 0,
                                               Ws + l * 128 * 128,
                                               asrc + l * 128,
                                               adst + l * 128);
        attn_scores_kernel<<<warp_blocks, 256>>>();
        aggregate_kernel<<<warp_blocks, 256>>>(bias + l * 128);
    }

    final_fc_kernel<<<(NN * 16 + 255) / 256, 256>>>(fcw, fcb, out);
}

// round 5
// speedup vs baseline: 1.2098x; 1.2056x over previous
#include <cuda_runtime.h>
#include <math.h>

#define NN 50000
#define EE 800000
#define MM (EE + NN)
#define HH 8
#define FF 128
#define NBLK ((NN + 255) / 256)   // 196

// ---------------- scratch (static __device__, no allocation) ----------------
__device__ __align__(16) float g_ha[NN * FF];   // post-GEMM h (per layer)
__device__ __align__(16) float g_hb[NN * FF];   // post-aggregation h (layer output)
__device__ __align__(16) float g_es[NN * HH];
__device__ __align__(16) float g_ed[NN * HH];
__device__ int   g_src[MM];                     // src ids sorted by dst (CSR)
__device__ int   g_rowptr[NN + 1];
__device__ int   g_cnt[NN];
__device__ int   g_cur[NN];
__device__ int   g_bsum[256];
__device__ int   g_is64;                        // edge_index dtype flag

// ---------------- dtype detection (parallel, 32 threads + ballot) ----------------
// jnp.int64 silently downcasts to int32 when x64 is disabled. Interpret the
// first 32 entries as int64; if all in [0, NN) it's genuinely int64 (an int32
// buffer read this way has hi~U[0,50000) per slot -> false-accept prob ~0).
__global__ void detect_kernel(const void* __restrict__ ei) {
    const long long* p64 = (const long long*)ei;
    long long v = p64[threadIdx.x];
    int bad = (v < 0 || v >= NN);
    unsigned m = __ballot_sync(0xffffffffu, bad);
    if (threadIdx.x == 0) g_is64 = (m == 0u);
}

__device__ __forceinline__ int load_idx(const void* __restrict__ ei, int pos) {
    if (g_is64) return (int)((const long long*)ei)[pos];
    return ((const int*)ei)[pos];
}

// ---------------- CSR build ----------------
__global__ void zero_cnt_kernel() {
    int i = blockIdx.x * blockDim.x + threadIdx.x;
    if (i < NN) g_cnt[i] = 0;
}

__global__ void count_kernel(const void* __restrict__ ei) {
    int i = blockIdx.x * blockDim.x + threadIdx.x;
    if (i >= MM) return;
    int dst = (i < EE) ? load_idx(ei, EE + i) : (i - EE);
    atomicAdd(&g_cnt[dst], 1);
}

// Two-level scan: scan1 (per-block exclusive scan + block sums),
// scan2 (scan of block sums), scan3 (add offsets, init g_cur, cap rowptr).
__global__ __launch_bounds__(256) void scan1_kernel() {
    int tid = threadIdx.x;
    int gid = blockIdx.x * 256 + tid;
    int v = (gid < NN) ? g_cnt[gid] : 0;
    int lane = tid & 31, w = tid >> 5;
    int x = v;
#pragma unroll
    for (int off = 1; off < 32; off <<= 1) {
        int y = __shfl_up_sync(0xffffffffu, x, off);
        if (lane >= off) x += y;
    }
    __shared__ int wsum[8];
    if (lane == 31) wsum[w] = x;
    __syncthreads();
    if (tid < 8) {
        int y = wsum[tid];
#pragma unroll
        for (int off = 1; off < 8; off <<= 1) {
            int z = __shfl_up_sync(0xffu, y, off);
            if (tid >= off) y += z;
        }
        wsum[tid] = y;
    }
    __syncthreads();
    int excl = x - v + (w > 0 ? wsum[w - 1] : 0);
    if (gid < NN) g_rowptr[gid] = excl;
    if (tid == 255) g_bsum[blockIdx.x] = wsum[7];
}

__global__ __launch_bounds__(256) void scan2_kernel() {
    int tid = threadIdx.x;
    int v = (tid < NBLK) ? g_bsum[tid] : 0;
    int lane = tid & 31, w = tid >> 5;
    int x = v;
#pragma unroll
    for (int off = 1; off < 32; off <<= 1) {
        int y = __shfl_up_sync(0xffffffffu, x, off);
        if (lane >= off) x += y;
    }
    __shared__ int wsum[8];
    if (lane == 31) wsum[w] = x;
    __syncthreads();
    if (tid < 8) {
        int y = wsum[tid];
#pragma unroll
        for (int off = 1; off < 8; off <<= 1) {
            int z = __shfl_up_sync(0xffu, y, off);
            if (tid >= off) y += z;
        }
        wsum[tid] = y;
    }
    __syncthreads();
    int excl = x - v + (w > 0 ? wsum[w - 1] : 0);
    if (tid < NBLK) g_bsum[tid] = excl;
}

__global__ __launch_bounds__(256) void scan3_kernel() {
    int gid = blockIdx.x * 256 + threadIdx.x;
    if (gid < NN) {
        int r = g_rowptr[gid] + g_bsum[blockIdx.x];
        g_rowptr[gid] = r;
        g_cur[gid] = r;
    }
    if (gid == 0) g_rowptr[NN] = MM;   // total is a compile-time constant
}

__global__ void fill_kernel(const void* __restrict__ ei) {
    int i = blockIdx.x * blockDim.x + threadIdx.x;
    if (i >= MM) return;
    int src, dst;
    if (i < EE) { src = load_idx(ei, i); dst = load_idx(ei, EE + i); }
    else        { src = dst = i - EE; }
    int pos = atomicAdd(&g_cur[dst], 1);
    g_src[pos] = src;
}

// ---------------- fused SGEMM + attention projections ----------------
// h = X @ W  [N,128]; e_src[n,h] = <h[n,h,:], a_src[h,:]>; same for e_dst.
#define BM 64
#define BK 32

__global__ __launch_bounds__(256)
void gemm_attn_kernel(const float* __restrict__ Xext, int useExt,
                      const float* __restrict__ W,
                      const float* __restrict__ asrc,
                      const float* __restrict__ adst) {
    __shared__ float Xs[BK][BM + 1];        // transposed x tile
    __shared__ float Ws_s[BK][128];
    __shared__ float es_sh[BM][HH];
    __shared__ float ed_sh[BM][HH];

    const float* X = useExt ? Xext : g_hb;
    int tid = threadIdx.x;
    int block_m = blockIdx.x * BM;

    for (int i = tid; i < BM * HH; i += 256) {
        (&es_sh[0][0])[i] = 0.0f;
        (&ed_sh[0][0])[i] = 0.0f;
    }

    int tm = tid >> 4;   // 0..15 -> rows tm*4..+3
    int tn = tid & 15;   // cols tn*8..+7

    float acc[4][8];
#pragma unroll
    for (int i = 0; i < 4; i++)
#pragma unroll
        for (int j = 0; j < 8; j++) acc[i][j] = 0.0f;

    for (int k0 = 0; k0 < FF; k0 += BK) {
        // load W tile 32x128
#pragma unroll
        for (int i = 0; i < 4; i++) {
            int idx = (tid + i * 256) * 4;       // 0..4092
            int kk = idx >> 7, cc = idx & 127;
            float4 v = *(const float4*)&W[(k0 + kk) * 128 + cc];
            *(float4*)&Ws_s[kk][cc] = v;
        }
        // load X tile 64x32 (transposed store)
#pragma unroll
        for (int i = 0; i < 2; i++) {
            int idx = (tid + i * 256) * 4;       // 0..2044
            int m = idx >> 5, kk = idx & 31;
            int node = block_m + m;
            float4 v = make_float4(0.f, 0.f, 0.f, 0.f);
            if (node < NN) v = *(const float4*)&X[node * FF + k0 + kk];
            Xs[kk + 0][m] = v.x; Xs[kk + 1][m] = v.y;
            Xs[kk + 2][m] = v.z; Xs[kk + 3][m] = v.w;
        }
        __syncthreads();
#pragma unroll
        for (int k = 0; k < BK; k++) {
            float4 b0 = *(const float4*)&Ws_s[k][tn * 8];
            float4 b1 = *(const float4*)&Ws_s[k][tn * 8 + 4];
            float bv[8] = {b0.x, b0.y, b0.z, b0.w, b1.x, b1.y, b1.z, b1.w};
            float av[4];
#pragma unroll
            for (int i = 0; i < 4; i++) av[i] = Xs[k][tm * 4 + i];
#pragma unroll
            for (int i = 0; i < 4; i++)
#pragma unroll
                for (int j = 0; j < 8; j++) acc[i][j] += av[i] * bv[j];
        }
        __syncthreads();
    }

    // epilogue: store h, accumulate attention projections
    int h = tn >> 1;             // head for this thread's 8 cols
    float as_[8], ad_[8];
#pragma unroll
    for (int j = 0; j < 8; j++) {
        int c = (tn * 8 + j) & 15;
        as_[j] = asrc[h * 16 + c];
        ad_[j] = adst[h * 16 + c];
    }
#pragma unroll
    for (int i = 0; i < 4; i++) {
        int m = tm * 4 + i;
        int node = block_m + m;
        if (node < NN) {
            float4 o0 = make_float4(acc[i][0], acc[i][1], acc[i][2], acc[i][3]);
            float4 o1 = make_float4(acc[i][4], acc[i][5], acc[i][6], acc[i][7]);
            *(float4*)&g_ha[node * FF + tn * 8] = o0;
            *(float4*)&g_ha[node * FF + tn * 8 + 4] = o1;
            float ps = 0.f, pd = 0.f;
#pragma unroll
            for (int j = 0; j < 8; j++) { ps += acc[i][j] * as_[j]; pd += acc[i][j] * ad_[j]; }
            atomicAdd(&es_sh[m][h], ps);
            atomicAdd(&ed_sh[m][h], pd);
        }
    }
    __syncthreads();
    for (int i = tid; i < BM * HH; i += 256) {
        int node = block_m + (i >> 3);
        if (node < NN) {
            g_es[node * HH + (i & 7)] = (&es_sh[0][0])[i];
            g_ed[node * HH + (i & 7)] = (&ed_sh[0][0])[i];
        }
    }
}

// ---------------- fused softmax + weighted gather + bias + ELU ----------------
// One warp per destination node.
// Pass 1 (max):   head = lane&7, slot = lane>>3, edges strided by 4.
// Pass 2 (gather): every lane walks all edges; lane computes w for head lane&7
//                  (one warp-wide MUFU per edge), then grabs the weight for its
//                  gather head (lane>>2, 4 channels per lane) via one SHFL.
// No g_w scratch, no atomics, denominator falls out of pass 2 for free.
__global__ __launch_bounds__(256)
void attn_agg_kernel(const float* __restrict__ bias) {
    int warp = blockIdx.x * (blockDim.x >> 5) + (threadIdx.x >> 5);
    if (warp >= NN) return;
    int lane = threadIdx.x & 31;
    int h8 = lane & 7;          // score-role head
    int slot = lane >> 3;
    int headq = lane >> 2;      // gather-role head (4 lanes per head)
    int r0 = g_rowptr[warp], r1 = g_rowptr[warp + 1];
    float edv = g_ed[warp * HH + h8];

    // pass 1: per-head max
    float m = -1e30f;
    for (int e = r0 + slot; e < r1; e += 4) {
        int s = g_src[e];
        float v = __ldg(&g_es[s * HH + h8]) + edv;
        v = v > 0.f ? v : 0.2f * v;
        m = fmaxf(m, v);
    }
    m = fmaxf(m, __shfl_xor_sync(0xffffffffu, m, 8));
    m = fmaxf(m, __shfl_xor_sync(0xffffffffu, m, 16));
    // every lane now holds max for head lane&7

    // pass 2: weights + gather
    float d = 0.f;
    float4 acc = make_float4(0.f, 0.f, 0.f, 0.f);
    for (int e = r0; e < r1; e++) {
        int s = g_src[e];
        float v = __ldg(&g_es[s * HH + h8]) + edv;
        v = v > 0.f ? v : 0.2f * v;
        float w = __expf(v - m);
        d += w;
        float wq = __shfl_sync(0xffffffffu, w, headq);
        float4 hv = *(const float4*)&g_ha[s * FF + lane * 4];
        acc.x += wq * hv.x; acc.y += wq * hv.y;
        acc.z += wq * hv.z; acc.w += wq * hv.w;
    }
    float dq = __shfl_sync(0xffffffffu, d, headq);
    float inv = 1.0f / (dq + 1e-16f);

    float4 b = *(const float4*)&bias[lane * 4];
    float4 o;
    o.x = acc.x * inv + b.x;
    o.y = acc.y * inv + b.y;
    o.z = acc.z * inv + b.z;
    o.w = acc.w * inv + b.w;
    o.x = o.x > 0.f ? o.x : expm1f(o.x);
    o.y = o.y > 0.f ? o.y : expm1f(o.y);
    o.z = o.z > 0.f ? o.z : expm1f(o.z);
    o.w = o.w > 0.f ? o.w : expm1f(o.w);
    *(float4*)&g_hb[warp * FF + lane * 4] = o;
}

// ---------------- final FC: out = h @ fc_w + fc_b  [N,16] ----------------
__global__ __launch_bounds__(256)
void final_fc_kernel(const float* __restrict__ fcw,
                     const float* __restrict__ fcb,
                     float* __restrict__ out) {
    int tid = blockIdx.x * blockDim.x + threadIdx.x;
    int node = tid >> 4;
    int c = tid & 15;
    if (node >= NN) return;
    const float* hr = g_hb + node * FF;
    float acc = fcb[c];
#pragma unroll 8
    for (int k = 0; k < FF; k++) acc += hr[k] * fcw[k * 16 + c];
    out[node * 16 + c] = acc;
}

// ---------------- launch ----------------
extern "C" void kernel_launch(void* const* d_in, const int* in_sizes, int n_in,
                              void* d_out, int out_size) {
    const float* x    = (const float*)d_in[0];
    const float* Ws   = (const float*)d_in[1];   // [3,128,128]
    const float* asrc = (const float*)d_in[2];   // [3,8,16]
    const float* adst = (const float*)d_in[3];
    const float* bias = (const float*)d_in[4];   // [3,128]
    const float* fcw  = (const float*)d_in[5];   // [128,16]
    const float* fcb  = (const float*)d_in[6];   // [16]
    const void*  ei   = (const void*)d_in[7];    // [2,E] int64 OR int32 (detected on device)
    float* out = (float*)d_out;

    // CSR build (once per launch, captured in graph)
    detect_kernel<<<1, 32>>>(ei);
    zero_cnt_kernel<<<(NN + 255) / 256, 256>>>();
    count_kernel<<<(MM + 255) / 256, 256>>>(ei);
    scan1_kernel<<<NBLK, 256>>>();
    scan2_kernel<<<1, 256>>>();
    scan3_kernel<<<NBLK, 256>>>();
    fill_kernel<<<(MM + 255) / 256, 256>>>(ei);

    int gemm_blocks = (NN + BM - 1) / BM;
    int warp_blocks = (NN + 7) / 8;

    for (int l = 0; l < 3; l++) {
        gemm_attn_kernel<<<gemm_blocks, 256>>>(x, l == 0 ? 1 : 0,
                                               Ws + l * 128 * 128,
                                               asrc + l * 128,
                                               adst + l * 128);
        attn_agg_kernel<<<warp_blocks, 256>>>(bias + l * 128);
    }

    final_fc_kernel<<<(NN * 16 + 255) / 256, 256>>>(fcw, fcb, out);
}

// round 6
// speedup vs baseline: 1.2157x; 1.0049x over previous
#include <cuda_runtime.h>
#include <math.h>

#define NN 50000
#define EE 800000
#define MM (EE + NN)
#define HH 8
#define FF 128
#define NBLK ((NN + 255) / 256)   // 196

// ---------------- scratch (static __device__, no allocation) ----------------
__device__ __align__(16) float g_ha[NN * FF];   // post-GEMM h (per layer)
__device__ __align__(16) float g_hb[NN * FF];   // post-aggregation h (layer output)
__device__ __align__(16) float g_es[NN * HH];
__device__ __align__(16) float g_ed[NN * HH];
__device__ int   g_src[MM];                     // src ids sorted by dst (CSR)
__device__ int   g_rowptr[NN + 1];
__device__ int   g_cnt[NN];
__device__ int   g_cur[NN];
__device__ int   g_bsum[256];
__device__ int   g_is64;                        // edge_index dtype flag

// ---------------- packed f32x2 helpers (FFMA2: 2 fp32 FMA per issue) ----------------
__device__ __forceinline__ unsigned long long pack2(float x, float y) {
    unsigned long long r;
    asm("mov.b64 %0, {%1, %2};" : "=l"(r) : "f"(x), "f"(y));
    return r;
}
__device__ __forceinline__ void fma2(unsigned long long& acc,
                                     unsigned long long a, unsigned long long b) {
    asm("fma.rn.f32x2 %0, %1, %2, %0;" : "+l"(acc) : "l"(a), "l"(b));
}
__device__ __forceinline__ float2 unpack2(unsigned long long v) {
    float2 f;
    asm("mov.b64 {%0, %1}, %2;" : "=f"(f.x), "=f"(f.y) : "l"(v));
    return f;
}

// ---------------- dtype detection (parallel, 32 threads + ballot) ----------------
// jnp.int64 silently downcasts to int32 when x64 is disabled. Interpret the
// first 32 entries as int64; if all in [0, NN) it's genuinely int64 (an int32
// buffer read this way has hi~U[0,50000) per slot -> false-accept prob ~0).
__global__ void detect_kernel(const void* __restrict__ ei) {
    const long long* p64 = (const long long*)ei;
    long long v = p64[threadIdx.x];
    int bad = (v < 0 || v >= NN);
    unsigned m = __ballot_sync(0xffffffffu, bad);
    if (threadIdx.x == 0) g_is64 = (m == 0u);
}

__device__ __forceinline__ int load_idx(const void* __restrict__ ei, int pos) {
    if (g_is64) return (int)((const long long*)ei)[pos];
    return ((const int*)ei)[pos];
}

// ---------------- CSR build ----------------
__global__ void zero_cnt_kernel() {
    int i = blockIdx.x * blockDim.x + threadIdx.x;
    if (i < NN) g_cnt[i] = 0;
}

__global__ void count_kernel(const void* __restrict__ ei) {
    int i = blockIdx.x * blockDim.x + threadIdx.x;
    if (i >= MM) return;
    int dst = (i < EE) ? load_idx(ei, EE + i) : (i - EE);
    atomicAdd(&g_cnt[dst], 1);
}

// Two-level scan
__global__ __launch_bounds__(256) void scan1_kernel() {
    int tid = threadIdx.x;
    int gid = blockIdx.x * 256 + tid;
    int v = (gid < NN) ? g_cnt[gid] : 0;
    int lane = tid & 31, w = tid >> 5;
    int x = v;
#pragma unroll
    for (int off = 1; off < 32; off <<= 1) {
        int y = __shfl_up_sync(0xffffffffu, x, off);
        if (lane >= off) x += y;
    }
    __shared__ int wsum[8];
    if (lane == 31) wsum[w] = x;
    __syncthreads();
    if (tid < 8) {
        int y = wsum[tid];
#pragma unroll
        for (int off = 1; off < 8; off <<= 1) {
            int z = __shfl_up_sync(0xffu, y, off);
            if (tid >= off) y += z;
        }
        wsum[tid] = y;
    }
    __syncthreads();
    int excl = x - v + (w > 0 ? wsum[w - 1] : 0);
    if (gid < NN) g_rowptr[gid] = excl;
    if (tid == 255) g_bsum[blockIdx.x] = wsum[7];
}

__global__ __launch_bounds__(256) void scan2_kernel() {
    int tid = threadIdx.x;
    int v = (tid < NBLK) ? g_bsum[tid] : 0;
    int lane = tid & 31, w = tid >> 5;
    int x = v;
#pragma unroll
    for (int off = 1; off < 32; off <<= 1) {
        int y = __shfl_up_sync(0xffffffffu, x, off);
        if (lane >= off) x += y;
    }
    __shared__ int wsum[8];
    if (lane == 31) wsum[w] = x;
    __syncthreads();
    if (tid < 8) {
        int y = wsum[tid];
#pragma unroll
        for (int off = 1; off < 8; off <<= 1) {
            int z = __shfl_up_sync(0xffu, y, off);
            if (tid >= off) y += z;
        }
        wsum[tid] = y;
    }
    __syncthreads();
    int excl = x - v + (w > 0 ? wsum[w - 1] : 0);
    if (tid < NBLK) g_bsum[tid] = excl;
}

__global__ __launch_bounds__(256) void scan3_kernel() {
    int gid = blockIdx.x * 256 + threadIdx.x;
    if (gid < NN) {
        int r = g_rowptr[gid] + g_bsum[blockIdx.x];
        g_rowptr[gid] = r;
        g_cur[gid] = r;
    }
    if (gid == 0) g_rowptr[NN] = MM;   // total is a compile-time constant
}

__global__ void fill_kernel(const void* __restrict__ ei) {
    int i = blockIdx.x * blockDim.x + threadIdx.x;
    if (i >= MM) return;
    int src, dst;
    if (i < EE) { src = load_idx(ei, i); dst = load_idx(ei, EE + i); }
    else        { src = dst = i - EE; }
    int pos = atomicAdd(&g_cur[dst], 1);
    g_src[pos] = src;
}

// ---------------- fused SGEMM + attention projections (FFMA2 inner loop) ----------------
#define BM 64
#define BK 32

__global__ __launch_bounds__(256)
void gemm_attn_kernel(const float* __restrict__ Xext, int useExt,
                      const float* __restrict__ W,
                      const float* __restrict__ asrc,
                      const float* __restrict__ adst) {
    __shared__ float Xs[BK][BM + 4];        // +4 keeps rows 16B-aligned for LDS.128
    __shared__ float Ws_s[BK][128];
    __shared__ float es_sh[BM][HH];
    __shared__ float ed_sh[BM][HH];

    const float* X = useExt ? Xext : g_hb;
    int tid = threadIdx.x;
    int block_m = blockIdx.x * BM;

    for (int i = tid; i < BM * HH; i += 256) {
        (&es_sh[0][0])[i] = 0.0f;
        (&ed_sh[0][0])[i] = 0.0f;
    }

    int tm = tid >> 4;   // 0..15 -> rows tm*4..+3
    int tn = tid & 15;   // cols tn*8..+7

    // acc pairs: accp[i][j] holds output cols {2j, 2j+1} for row tm*4+i
    unsigned long long accp[4][4];
#pragma unroll
    for (int i = 0; i < 4; i++)
#pragma unroll
        for (int j = 0; j < 4; j++) accp[i][j] = 0ull;

    for (int k0 = 0; k0 < FF; k0 += BK) {
        // load W tile 32x128
#pragma unroll
        for (int i = 0; i < 4; i++) {
            int idx = (tid + i * 256) * 4;       // 0..4092
            int kk = idx >> 7, cc = idx & 127;
            float4 v = *(const float4*)&W[(k0 + kk) * 128 + cc];
            *(float4*)&Ws_s[kk][cc] = v;
        }
        // load X tile 64x32 (transposed store)
#pragma unroll
        for (int i = 0; i < 2; i++) {
            int idx = (tid + i * 256) * 4;       // 0..2044
            int m = idx >> 5, kk = idx & 31;
            int node = block_m + m;
            float4 v = make_float4(0.f, 0.f, 0.f, 0.f);
            if (node < NN) v = *(const float4*)&X[node * FF + k0 + kk];
            Xs[kk + 0][m] = v.x; Xs[kk + 1][m] = v.y;
            Xs[kk + 2][m] = v.z; Xs[kk + 3][m] = v.w;
        }
        __syncthreads();
#pragma unroll
        for (int k = 0; k < BK; k++) {
            // B fragment: 8 cols = 4 f32x2 (two LDS.128)
            const unsigned long long* bp =
                (const unsigned long long*)&Ws_s[k][tn * 8];
            unsigned long long b0 = bp[0], b1 = bp[1], b2 = bp[2], b3 = bp[3];
            // A fragment: 4 rows via one LDS.128, replicated into both halves
            float4 av = *(const float4*)&Xs[k][tm * 4];
            unsigned long long a0 = pack2(av.x, av.x);
            unsigned long long a1 = pack2(av.y, av.y);
            unsigned long long a2 = pack2(av.z, av.z);
            unsigned long long a3 = pack2(av.w, av.w);
            fma2(accp[0][0], a0, b0); fma2(accp[0][1], a0, b1);
            fma2(accp[0][2], a0, b2); fma2(accp[0][3], a0, b3);
            fma2(accp[1][0], a1, b0); fma2(accp[1][1], a1, b1);
            fma2(accp[1][2], a1, b2); fma2(accp[1][3], a1, b3);
            fma2(accp[2][0], a2, b0); fma2(accp[2][1], a2, b1);
            fma2(accp[2][2], a2, b2); fma2(accp[2][3], a2, b3);
            fma2(accp[3][0], a3, b0); fma2(accp[3][1], a3, b1);
            fma2(accp[3][2], a3, b2); fma2(accp[3][3], a3, b3);
        }
        __syncthreads();
    }

    // epilogue: store h, accumulate attention projections
    int h = tn >> 1;             // head for this thread's 8 cols
    float as_[8], ad_[8];
#pragma unroll
    for (int j = 0; j < 8; j++) {
        int c = (tn * 8 + j) & 15;
        as_[j] = asrc[h * 16 + c];
        ad_[j] = adst[h * 16 + c];
    }
#pragma unroll
    for (int i = 0; i < 4; i++) {
        int m = tm * 4 + i;
        int node = block_m + m;
        if (node < NN) {
            float2 c0 = unpack2(accp[i][0]);
            float2 c1 = unpack2(accp[i][1]);
            float2 c2 = unpack2(accp[i][2]);
            float2 c3 = unpack2(accp[i][3]);
            float accv[8] = {c0.x, c0.y, c1.x, c1.y, c2.x, c2.y, c3.x, c3.y};
            float4 o0 = make_float4(accv[0], accv[1], accv[2], accv[3]);
            float4 o1 = make_float4(accv[4], accv[5], accv[6], accv[7]);
            *(float4*)&g_ha[node * FF + tn * 8] = o0;
            *(float4*)&g_ha[node * FF + tn * 8 + 4] = o1;
            float ps = 0.f, pd = 0.f;
#pragma unroll
            for (int j = 0; j < 8; j++) { ps += accv[j] * as_[j]; pd += accv[j] * ad_[j]; }
            atomicAdd(&es_sh[m][h], ps);
            atomicAdd(&ed_sh[m][h], pd);
        }
    }
    __syncthreads();
    for (int i = tid; i < BM * HH; i += 256) {
        int node = block_m + (i >> 3);
        if (node < NN) {
            g_es[node * HH + (i & 7)] = (&es_sh[0][0])[i];
            g_ed[node * HH + (i & 7)] = (&ed_sh[0][0])[i];
        }
    }
}

// ---------------- fused softmax + weighted gather + bias + ELU ----------------
// One warp per destination node. Pass 1: per-head max (head=lane&7).
// Pass 2: every lane walks all edges; lane computes w for head lane&7, then
// grabs the weight for its gather head (lane>>2) via one SHFL.
__global__ __launch_bounds__(256)
void attn_agg_kernel(const float* __restrict__ bias) {
    int warp = blockIdx.x * (blockDim.x >> 5) + (threadIdx.x >> 5);
    if (warp >= NN) return;
    int lane = threadIdx.x & 31;
    int h8 = lane & 7;          // score-role head
    int slot = lane >> 3;
    int headq = lane >> 2;      // gather-role head (4 lanes per head)
    int r0 = g_rowptr[warp], r1 = g_rowptr[warp + 1];
    float edv = g_ed[warp * HH + h8];

    // pass 1: per-head max
    float m = -1e30f;
    for (int e = r0 + slot; e < r1; e += 4) {
        int s = g_src[e];
        float v = __ldg(&g_es[s * HH + h8]) + edv;
        v = v > 0.f ? v : 0.2f * v;
        m = fmaxf(m, v);
    }
    m = fmaxf(m, __shfl_xor_sync(0xffffffffu, m, 8));
    m = fmaxf(m, __shfl_xor_sync(0xffffffffu, m, 16));

    // pass 2: weights + gather
    float d = 0.f;
    float4 acc = make_float4(0.f, 0.f, 0.f, 0.f);
    for (int e = r0; e < r1; e++) {
        int s = g_src[e];
        float v = __ldg(&g_es[s * HH + h8]) + edv;
        v = v > 0.f ? v : 0.2f * v;
        float w = __expf(v - m);
        d += w;
        float wq = __shfl_sync(0xffffffffu, w, headq);
        float4 hv = *(const float4*)&g_ha[s * FF + lane * 4];
        acc.x += wq * hv.x; acc.y += wq * hv.y;
        acc.z += wq * hv.z; acc.w += wq * hv.w;
    }
    float dq = __shfl_sync(0xffffffffu, d, headq);
    float inv = 1.0f / (dq + 1e-16f);

    float4 b = *(const float4*)&bias[lane * 4];
    float4 o;
    o.x = acc.x * inv + b.x;
    o.y = acc.y * inv + b.y;
    o.z = acc.z * inv + b.z;
    o.w = acc.w * inv + b.w;
    o.x = o.x > 0.f ? o.x : expm1f(o.x);
    o.y = o.y > 0.f ? o.y : expm1f(o.y);
    o.z = o.z > 0.f ? o.z : expm1f(o.z);
    o.w = o.w > 0.f ? o.w : expm1f(o.w);
    *(float4*)&g_hb[warp * FF + lane * 4] = o;
}

// ---------------- final FC: out = h @ fc_w + fc_b  [N,16] ----------------
__global__ __launch_bounds__(256)
void final_fc_kernel(const float* __restrict__ fcw,
                     const float* __restrict__ fcb,
                     float* __restrict__ out) {
    int tid = blockIdx.x * blockDim.x + threadIdx.x;
    int node = tid >> 4;
    int c = tid & 15;
    if (node >= NN) return;
    const float* hr = g_hb + node * FF;
    float acc = fcb[c];
#pragma unroll 8
    for (int k = 0; k < FF; k++) acc += hr[k] * fcw[k * 16 + c];
    out[node * 16 + c] = acc;
}

// ---------------- launch ----------------
extern "C" void kernel_launch(void* const* d_in, const int* in_sizes, int n_in,
                              void* d_out, int out_size) {
    const float* x    = (const float*)d_in[0];
    const float* Ws   = (const float*)d_in[1];   // [3,128,128]
    const float* asrc = (const float*)d_in[2];   // [3,8,16]
    const float* adst = (const float*)d_in[3];
    const float* bias = (const float*)d_in[4];   // [3,128]
    const float* fcw  = (const float*)d_in[5];   // [128,16]
    const float* fcb  = (const float*)d_in[6];   // [16]
    const void*  ei   = (const void*)d_in[7];    // [2,E] int64 OR int32 (detected on device)
    float* out = (float*)d_out;

    // CSR build (once per launch, captured in graph)
    detect_kernel<<<1, 32>>>(ei);
    zero_cnt_kernel<<<(NN + 255) / 256, 256>>>();
    count_kernel<<<(MM + 255) / 256, 256>>>(ei);
    scan1_kernel<<<NBLK, 256>>>();
    scan2_kernel<<<1, 256>>>();
    scan3_kernel<<<NBLK, 256>>>();
    fill_kernel<<<(MM + 255) / 256, 256>>>(ei);

    int gemm_blocks = (NN + BM - 1) / BM;
    int warp_blocks = (NN + 7) / 8;

    for (int l = 0; l < 3; l++) {
        gemm_attn_kernel<<<gemm_blocks, 256>>>(x, l == 0 ? 1 : 0,
                                               Ws + l * 128 * 128,
                                               asrc + l * 128,
                                               adst + l * 128);
        attn_agg_kernel<<<warp_blocks, 256>>>(bias + l * 128);
    }

    final_fc_kernel<<<(NN * 16 + 255) / 256, 256>>>(fcw, fcb, out);
}